// round 10
// baseline (speedup 1.0000x reference)
#include <cuda_runtime.h>
#include <cstdint>

#define C_IN  64
#define OC    64
#define KNPTS 9
#define PLANE 16384
#define KTOT  576

#define THREADS 512                 // 8 producer + 8 consumer warps
#define PIXB   128                  // pixels per block (M)
#define NBLK   (4 * PLANE / PIXB)   // 512

// ---- scratch (__device__ globals: allocation is forbidden) ----
__device__ float    g_xhwc[(size_t)4 * PLANE * C_IN];   // NHWC x
__device__ uint32_t g_w0[KNPTS * OC * 32];              // bf16-hi pairs [kn][oc][kp]
__device__ uint32_t g_w1[KNPTS * OC * 32];              // bf16-lo pairs

// ---- dynamic smem layout (bytes): double-buffered tiles ----
#define SM_AH     0                 // A hi [2] : 2 x 16384
#define SM_AL     32768             // A lo [2] : 2 x 16384
#define SM_BH     65536             // B hi [2] : 2 x 8192
#define SM_BL     81920             // B lo [2] : 2 x 8192
#define SM_INTERP 98304             // 1152 x 12B = 13824
#define SM_MBAR   112128            // 4 mbarriers (full0,full1,empty0,empty1)
#define SM_TOTAL  112160
#define CS_STRIDE 132               // epilogue C stage row stride (floats)

// word-index swizzles (swizzle bits 2-4 only; 16B groups stay contiguous)
#define AIDX(p, kp)  (((p)  << 5) + ((kp) ^ (((p)  & 7) << 2)))
#define BIDX(oc, kp) (((oc) << 5) + ((kp) ^ (((oc) & 7) << 2)))

__device__ __forceinline__ uint32_t pack_bf16x2(float lo, float hi) {
    uint32_t r;   // d.hi = cvt(hi), d.lo = cvt(lo)
    asm("cvt.rn.bf16x2.f32 %0, %1, %2;" : "=r"(r) : "f"(hi), "f"(lo));
    return r;
}
__device__ __forceinline__ float unpack_lo(uint32_t w) { return __uint_as_float(w << 16); }
__device__ __forceinline__ float unpack_hi(uint32_t w) { return __uint_as_float(w & 0xFFFF0000u); }

__device__ __forceinline__ uint32_t smem_u32(const void* p) {
    uint32_t a;
    asm("{ .reg .u64 t; cvta.to.shared.u64 t, %1; cvt.u32.u64 %0, t; }" : "=r"(a) : "l"(p));
    return a;
}
__device__ __forceinline__ void ldm4(uint32_t* d, uint32_t addr) {
    asm volatile("ldmatrix.sync.aligned.m8n8.x4.shared.b16 {%0,%1,%2,%3}, [%4];"
                 : "=r"(d[0]), "=r"(d[1]), "=r"(d[2]), "=r"(d[3]) : "r"(addr));
}
__device__ __forceinline__ void ldm2(uint32_t* d, uint32_t addr) {
    asm volatile("ldmatrix.sync.aligned.m8n8.x2.shared.b16 {%0,%1}, [%2];"
                 : "=r"(d[0]), "=r"(d[1]) : "r"(addr));
}
__device__ __forceinline__ void mbar_init(uint32_t a, uint32_t cnt) {
    asm volatile("mbarrier.init.shared.b64 [%0], %1;" :: "r"(a), "r"(cnt) : "memory");
}
__device__ __forceinline__ void mbar_arrive(uint32_t a) {
    asm volatile("mbarrier.arrive.shared.b64 _, [%0];" :: "r"(a) : "memory");
}
__device__ __forceinline__ void mbar_wait(uint32_t a, uint32_t parity) {
    asm volatile(
        "{\n\t.reg .pred P;\n\tW%=:\n\t"
        "mbarrier.try_wait.parity.acquire.cta.shared::cta.b64 P, [%0], %1, 0x989680;\n\t"
        "@P bra.uni D%=;\n\tbra.uni W%=;\n\tD%=:\n\t}"
        :: "r"(a), "r"(parity) : "memory");
}

#define MMA(C, A, B)                                                            \
    asm volatile("mma.sync.aligned.m16n8k16.row.col.f32.bf16.bf16.f32 "         \
                 "{%0,%1,%2,%3},{%4,%5,%6,%7},{%8,%9},{%0,%1,%2,%3};"           \
                 : "+f"(C[0]), "+f"(C[1]), "+f"(C[2]), "+f"(C[3])               \
                 : "r"(A[0]), "r"(A[1]), "r"(A[2]), "r"(A[3]), "r"(B[0]), "r"(B[1]))

// ---------------- NCHW -> NHWC transpose (64-pixel tiles, 1024 blocks) ----------------
__global__ __launch_bounds__(256)
void nchw_to_nhwc_kernel(const float* __restrict__ x)
{
    __shared__ float t[64][65];
    const int n   = blockIdx.x >> 8;             // 256 tiles per image
    const int hw0 = (blockIdx.x & 255) << 6;     // 64 pixels per tile
    const int tid = threadIdx.x;
    const float* xn = x + ((size_t)n << 20);
#pragma unroll
    for (int k = 0; k < 4; k++) {
        const int idx = tid + k * 256;           // 1024 float4 loads
        const int c = idx >> 4, q = idx & 15;
        const float4 v = *(const float4*)(xn + ((size_t)c << 14) + hw0 + 4 * q);
        t[c][4 * q] = v.x; t[c][4 * q + 1] = v.y; t[c][4 * q + 2] = v.z; t[c][4 * q + 3] = v.w;
    }
    __syncthreads();
    float* dst = g_xhwc + (((size_t)n << 14) + hw0) * 64;
#pragma unroll
    for (int k = 0; k < 4; k++) {
        const int idx = tid + k * 256;           // 1024 float4 stores
        const int p = idx >> 4, cq = idx & 15;
        float4 v;
        v.x = t[4 * cq][p]; v.y = t[4 * cq + 1][p]; v.z = t[4 * cq + 2][p]; v.w = t[4 * cq + 3][p];
        *(float4*)(dst + (size_t)p * 64 + 4 * cq) = v;
    }
}

// ------- weight: permute to [kn][oc][kp] + bf16 hi/lo split (packed pairs) -------
__global__ __launch_bounds__(256)
void wsplit_kernel(const float* __restrict__ w)
{
    const int i = blockIdx.x * 256 + threadIdx.x;   // i = kn*2048 + oc*32 + kp
    if (i < KNPTS * OC * 32) {
        const int kn = i >> 11, r = i & 2047;
        const int oc = r >> 5, kp = r & 31;
        const int c = 2 * kp;
        const float v0 = w[oc * KTOT + c * KNPTS + kn];
        const float v1 = w[oc * KTOT + (c + 1) * KNPTS + kn];
        const uint32_t h = pack_bf16x2(v0, v1);
        g_w0[i] = h;
        g_w1[i] = pack_bf16x2(v0 - unpack_lo(h), v1 - unpack_hi(h));
    }
}

// ------------ main kernel: warp-specialized sample -> 3xBF16 mma.sync ------------
struct Interp { short x0, y0; float fx, fy; };

extern __shared__ char smem[];

__global__ __launch_bounds__(THREADS, 1)
void dcn_ws_kernel(const float* __restrict__ offset, float* __restrict__ out)
{
    const int tid  = threadIdx.x;
    const int wid  = tid >> 5;
    const int lane = tid & 31;
    const int n       = blockIdx.x >> 7;            // 128 blocks per image
    const int pixbase = (blockIdx.x & 127) << 7;    // 128 consecutive pixels

    const float* offn = offset + (size_t)n * (KNPTS * 2) * PLANE;
    const float* xb   = g_xhwc + (((size_t)n) << 14) * 64;
    Interp* interp = (Interp*)(smem + SM_INTERP);

    const uint32_t sb   = smem_u32(smem);
    const uint32_t full0  = sb + SM_MBAR,      full1  = sb + SM_MBAR + 8;
    const uint32_t empty0 = sb + SM_MBAR + 16, empty1 = sb + SM_MBAR + 24;

    if (tid == 0) {
        mbar_init(full0, 256);  mbar_init(full1, 256);
        mbar_init(empty0, 256); mbar_init(empty1, 256);
    }

    // ---- interp metadata (all 512 threads) ----
    for (int it = tid; it < PIXB * KNPTS; it += THREADS) {
        const int p  = it / 9;
        const int kn = it - p * 9;
        const int pix = pixbase + p;
        const int oh = pix >> 7, ow = pix & 127;
        const float iy = (float)oh + offn[(2 * kn)     * PLANE + pix];
        const float ix = (float)ow + offn[(2 * kn + 1) * PLANE + pix];
        const float y0f = floorf(iy), x0f = floorf(ix);
        Interp t; t.x0 = (short)x0f; t.y0 = (short)y0f; t.fx = ix - x0f; t.fy = iy - y0f;
        interp[it] = t;
    }
    __syncthreads();   // interp + mbarrier init visible to all

    if (wid < 8) {
        // ================= PRODUCERS (threads 0..255) =================
        const int tg = tid >> 4;        // task group 0..15
        const int lh = tid & 15;        // channel quad owner
        int pe0 = 0, pe1 = 0;           // empty-wait parities per buffer

        for (int kn = 0; kn < KNPTS; kn++) {
            const int buf = kn & 1;
            if (kn >= 2) {
                if (buf == 0) { mbar_wait(empty0, pe0); pe0 ^= 1; }
                else          { mbar_wait(empty1, pe1); pe1 ^= 1; }
            }
            uint32_t* A0 = (uint32_t*)(smem + SM_AH + buf * 16384);
            uint32_t* A1 = (uint32_t*)(smem + SM_AL + buf * 16384);
            uint32_t* B0 = (uint32_t*)(smem + SM_BH + buf * 8192);
            uint32_t* B1 = (uint32_t*)(smem + SM_BL + buf * 8192);

            // sample 128 pixels x 64 ch -> bf16 hi/lo, swizzled STS.64
#pragma unroll
            for (int it = 0; it < 8; it++) {
                const int p = it * 16 + tg;
                const Interp t = interp[p * 9 + kn];
                const int x0 = t.x0, y0 = t.y0, x1 = x0 + 1, y1 = y0 + 1;
                const float wx1 = t.fx, wy1 = t.fy;
                const float wx0 = 1.f - wx1, wy0 = 1.f - wy1;
                const float mx0 = ((unsigned)x0 < 128u) ? 1.f : 0.f;
                const float mx1 = ((unsigned)x1 < 128u) ? 1.f : 0.f;
                const float my0 = ((unsigned)y0 < 128u) ? 1.f : 0.f;
                const float my1 = ((unsigned)y1 < 128u) ? 1.f : 0.f;
                const int cx0 = min(max((int)x0, 0), 127), cx1 = min(max((int)x1, 0), 127);
                const int cy0 = min(max((int)y0, 0), 127), cy1 = min(max((int)y1, 0), 127);
                const float w00 = wx0 * wy0 * mx0 * my0;
                const float w01 = wx1 * wy0 * mx1 * my0;
                const float w10 = wx0 * wy1 * mx0 * my1;
                const float w11 = wx1 * wy1 * mx1 * my1;
                const float4 a = *(const float4*)(xb + (((cy0 << 7) + cx0) << 6) + 4 * lh);
                const float4 b = *(const float4*)(xb + (((cy0 << 7) + cx1) << 6) + 4 * lh);
                const float4 c = *(const float4*)(xb + (((cy1 << 7) + cx0) << 6) + 4 * lh);
                const float4 d = *(const float4*)(xb + (((cy1 << 7) + cx1) << 6) + 4 * lh);
                float v0 = w00 * a.x + w01 * b.x + w10 * c.x + w11 * d.x;
                float v1 = w00 * a.y + w01 * b.y + w10 * c.y + w11 * d.y;
                float v2 = w00 * a.z + w01 * b.z + w10 * c.z + w11 * d.z;
                float v3 = w00 * a.w + w01 * b.w + w10 * c.w + w11 * d.w;
                uint2 hi, lo;
                hi.x = pack_bf16x2(v0, v1);
                hi.y = pack_bf16x2(v2, v3);
                lo.x = pack_bf16x2(v0 - unpack_lo(hi.x), v1 - unpack_hi(hi.x));
                lo.y = pack_bf16x2(v2 - unpack_lo(hi.y), v3 - unpack_hi(hi.y));
                const int wix = AIDX(p, 2 * lh);
                *(uint2*)&A0[wix] = hi;
                *(uint2*)&A1[wix] = lo;
            }
            // stage weight chunk
#pragma unroll
            for (int k = 0; k < 4; k++) {
                const int i = tid + k * 256;
                const int oc = i >> 4, q = i & 15;
                const int wix = BIDX(oc, 2 * q);
                const int gi  = (kn << 11) + (oc << 5) + 2 * q;
                *(uint2*)&B0[wix] = *(const uint2*)&g_w0[gi];
                *(uint2*)&B1[wix] = *(const uint2*)&g_w1[gi];
            }
            mbar_arrive(buf == 0 ? full0 : full1);   // release: stores visible
        }
    } else {
        // ================= CONSUMERS (threads 256..511) =================
        const int cw = wid - 8;
        const int m0 = (cw & 3) * 32;
        const int n0 = (cw >> 2) * 32;
        const int r  = lane >> 2;
        const int u  = lane & 3;
        const int l7   = lane & 7;
        const int swz  = l7 << 2;
        const int arow0 = m0 + l7 + (((lane >> 3) & 1) << 3);
        const int kbA   = ((lane >> 4) & 1) << 2;
        const int browl = n0 + l7;
        const int kbB   = ((lane >> 3) & 1) << 2;

        float acc[2][4][4];
#pragma unroll
        for (int mt = 0; mt < 2; mt++)
#pragma unroll
            for (int nt = 0; nt < 4; nt++)
#pragma unroll
                for (int q = 0; q < 4; q++) acc[mt][nt][q] = 0.f;

        int pf0 = 0, pf1 = 0;   // full-wait parities per buffer
        for (int kn = 0; kn < KNPTS; kn++) {
            const int buf = kn & 1;
            if (buf == 0) { mbar_wait(full0, pf0); pf0 ^= 1; }
            else          { mbar_wait(full1, pf1); pf1 ^= 1; }
            const uint32_t a0b = sb + SM_AH + buf * 16384;
            const uint32_t a1b = sb + SM_AL + buf * 16384;
            const uint32_t b0b = sb + SM_BH + buf * 8192;
            const uint32_t b1b = sb + SM_BL + buf * 8192;

#pragma unroll
            for (int ks = 0; ks < 4; ks++) {
                uint32_t a0[2][4], a1[2][4];
#pragma unroll
                for (int mt = 0; mt < 2; mt++) {
                    const int row = arow0 + mt * 16;
                    const uint32_t off =
                        (uint32_t)(((row << 5) + ((ks * 8 + kbA) ^ swz)) << 2);
                    ldm4(a0[mt], a0b + off);
                    ldm4(a1[mt], a1b + off);
                }
                uint32_t b0[4][2], b1[4][2];
#pragma unroll
                for (int nt = 0; nt < 4; nt++) {
                    const int row = browl + nt * 8;
                    const uint32_t off =
                        (uint32_t)(((row << 5) + ((ks * 8 + kbB) ^ swz)) << 2);
                    ldm2(b0[nt], b0b + off);
                    ldm2(b1[nt], b1b + off);
                }
#pragma unroll
                for (int mt = 0; mt < 2; mt++)
#pragma unroll
                    for (int nt = 0; nt < 4; nt++) {
                        MMA(acc[mt][nt], a1[mt], b0[nt]);   // lo-x * hi-w
                        MMA(acc[mt][nt], a0[mt], b1[nt]);   // hi-x * lo-w
                        MMA(acc[mt][nt], a0[mt], b0[nt]);   // hi-x * hi-w
                    }
            }
            mbar_arrive(buf == 0 ? empty0 : empty1);
        }

        // ---- epilogue (consumers only): stage C, coalesced STG.128 ----
        asm volatile("bar.sync 1, 256;" ::: "memory");   // all consumer GEMMs done
        float* Cs = (float*)smem;   // reuse A region (producers finished)
#pragma unroll
        for (int mt = 0; mt < 2; mt++)
#pragma unroll
            for (int nt = 0; nt < 4; nt++) {
                const int p  = m0 + mt * 16 + r;
                const int oc = n0 + nt * 8 + 2 * u;
                Cs[oc * CS_STRIDE + p]           = acc[mt][nt][0];
                Cs[(oc + 1) * CS_STRIDE + p]     = acc[mt][nt][1];
                Cs[oc * CS_STRIDE + p + 8]       = acc[mt][nt][2];
                Cs[(oc + 1) * CS_STRIDE + p + 8] = acc[mt][nt][3];
            }
        asm volatile("bar.sync 1, 256;" ::: "memory");
        float* ob = out + (((size_t)n * OC) << 14) + pixbase;
        const int ctid = tid - 256;
#pragma unroll
        for (int k = 0; k < 8; k++) {
            const int idx = ctid + k * 256;
            const int oc = idx >> 5, fq = idx & 31;
            const float4 v = *(const float4*)(Cs + oc * CS_STRIDE + fq * 4);
            *(float4*)(ob + ((size_t)oc << 14) + fq * 4) = v;
        }
    }
}

extern "C" void kernel_launch(void* const* d_in, const int* in_sizes, int n_in,
                              void* d_out, int out_size)
{
    const float* x      = (const float*)d_in[0];   // (4, 64, 128, 128)
    const float* offset = (const float*)d_in[1];   // (4, 18, 128, 128)
    const float* weight = (const float*)d_in[2];   // (64, 64, 9)
    float* out = (float*)d_out;                    // (4, 64, 128, 128)
    (void)in_sizes; (void)n_in; (void)out_size;

    static int smem_set = 0;
    if (!smem_set) {
        cudaFuncSetAttribute(dcn_ws_kernel,
                             cudaFuncAttributeMaxDynamicSharedMemorySize, SM_TOTAL);
        smem_set = 1;
    }
    nchw_to_nhwc_kernel<<<4 * 256, 256>>>(x);
    wsplit_kernel<<<(KNPTS * OC * 32 + 255) / 256, 256>>>(weight);
    dcn_ws_kernel<<<NBLK, THREADS, SM_TOTAL>>>(offset, out);
}

// round 11
// speedup vs baseline: 1.2917x; 1.2917x over previous
#include <cuda_runtime.h>
#include <cstdint>

#define C_IN  64
#define OC    64
#define KNPTS 9
#define PLANE 16384
#define KTOT  576

#define THREADS 256
#define PIXB   128                  // pixels per block (M) = one image row
#define NBLK   (4 * PLANE / PIXB)   // 512

// ---- scratch (__device__ globals: allocation is forbidden) ----
__device__ float    g_xhwc[(size_t)4 * PLANE * C_IN];   // NHWC x
__device__ uint32_t g_w0[KNPTS * OC * 32];              // bf16-hi pairs [kn][oc][kp]
__device__ uint32_t g_w1[KNPTS * OC * 32];              // bf16-lo pairs

// ---- dynamic smem layout (bytes): double-buffered tiles ----
#define SM_AH     0                 // A hi [2] : 2 x 16384
#define SM_AL     32768             // A lo [2] : 2 x 16384
#define SM_BH     65536             // B hi [2] : 2 x 8192
#define SM_BL     81920             // B lo [2] : 2 x 8192
#define SM_TOTAL  98304
#define CS_STRIDE 132               // epilogue C stage row stride (floats)

// word-index swizzles (swizzle bits 2-4 only; 16B groups stay contiguous)
#define AIDX(p, kp)  (((p)  << 5) + ((kp) ^ (((p)  & 7) << 2)))
#define BIDX(oc, kp) (((oc) << 5) + ((kp) ^ (((oc) & 7) << 2)))

__device__ __forceinline__ uint32_t pack_bf16x2(float lo, float hi) {
    uint32_t r;   // d.hi = cvt(hi), d.lo = cvt(lo)
    asm("cvt.rn.bf16x2.f32 %0, %1, %2;" : "=r"(r) : "f"(hi), "f"(lo));
    return r;
}
__device__ __forceinline__ float unpack_lo(uint32_t w) { return __uint_as_float(w << 16); }
__device__ __forceinline__ float unpack_hi(uint32_t w) { return __uint_as_float(w & 0xFFFF0000u); }

__device__ __forceinline__ uint32_t smem_u32(const void* p) {
    uint32_t a;
    asm("{ .reg .u64 t; cvta.to.shared.u64 t, %1; cvt.u32.u64 %0, t; }" : "=r"(a) : "l"(p));
    return a;
}
__device__ __forceinline__ void ldm4(uint32_t* d, uint32_t addr) {
    asm volatile("ldmatrix.sync.aligned.m8n8.x4.shared.b16 {%0,%1,%2,%3}, [%4];"
                 : "=r"(d[0]), "=r"(d[1]), "=r"(d[2]), "=r"(d[3]) : "r"(addr));
}
__device__ __forceinline__ void ldm2(uint32_t* d, uint32_t addr) {
    asm volatile("ldmatrix.sync.aligned.m8n8.x2.shared.b16 {%0,%1}, [%2];"
                 : "=r"(d[0]), "=r"(d[1]) : "r"(addr));
}

#define MMA(C, A, B)                                                            \
    asm volatile("mma.sync.aligned.m16n8k16.row.col.f32.bf16.bf16.f32 "         \
                 "{%0,%1,%2,%3},{%4,%5,%6,%7},{%8,%9},{%0,%1,%2,%3};"           \
                 : "+f"(C[0]), "+f"(C[1]), "+f"(C[2]), "+f"(C[3])               \
                 : "r"(A[0]), "r"(A[1]), "r"(A[2]), "r"(A[3]), "r"(B[0]), "r"(B[1]))

// ---------------- NCHW -> NHWC transpose (64-pixel tiles, 1024 blocks) ----------------
__global__ __launch_bounds__(256)
void nchw_to_nhwc_kernel(const float* __restrict__ x)
{
    __shared__ float t[64][65];
    const int n   = blockIdx.x >> 8;
    const int hw0 = (blockIdx.x & 255) << 6;
    const int tid = threadIdx.x;
    const float* xn = x + ((size_t)n << 20);
#pragma unroll
    for (int k = 0; k < 4; k++) {
        const int idx = tid + k * 256;
        const int c = idx >> 4, q = idx & 15;
        const float4 v = *(const float4*)(xn + ((size_t)c << 14) + hw0 + 4 * q);
        t[c][4 * q] = v.x; t[c][4 * q + 1] = v.y; t[c][4 * q + 2] = v.z; t[c][4 * q + 3] = v.w;
    }
    __syncthreads();
    float* dst = g_xhwc + (((size_t)n << 14) + hw0) * 64;
#pragma unroll
    for (int k = 0; k < 4; k++) {
        const int idx = tid + k * 256;
        const int p = idx >> 4, cq = idx & 15;
        float4 v;
        v.x = t[4 * cq][p]; v.y = t[4 * cq + 1][p]; v.z = t[4 * cq + 2][p]; v.w = t[4 * cq + 3][p];
        *(float4*)(dst + (size_t)p * 64 + 4 * cq) = v;
    }
}

// ------- weight: permute to [kn][oc][kp] + bf16 hi/lo split (packed pairs) -------
__global__ __launch_bounds__(256)
void wsplit_kernel(const float* __restrict__ w)
{
    const int i = blockIdx.x * 256 + threadIdx.x;   // i = kn*2048 + oc*32 + kp
    if (i < KNPTS * OC * 32) {
        const int kn = i >> 11, r = i & 2047;
        const int oc = r >> 5, kp = r & 31;
        const int c = 2 * kp;
        const float v0 = w[oc * KTOT + c * KNPTS + kn];
        const float v1 = w[oc * KTOT + (c + 1) * KNPTS + kn];
        const uint32_t h = pack_bf16x2(v0, v1);
        g_w0[i] = h;
        g_w1[i] = pack_bf16x2(v0 - unpack_lo(h), v1 - unpack_hi(h));
    }
}

// ---- main kernel: double-buffered software pipeline, 3xBF16 mma.sync ----
extern __shared__ char smem[];

__global__ __launch_bounds__(THREADS, 2)
void dcn_mma_kernel(const float* __restrict__ offset, float* __restrict__ out)
{
    const int tid  = threadIdx.x;
    const int wid  = tid >> 5;
    const int lane = tid & 31;
    const int n       = blockIdx.x >> 7;            // 128 blocks per image
    const int pixbase = (blockIdx.x & 127) << 7;    // one full image row
    const int ohc     = pixbase >> 7;               // constant oh for this block

    const float* offn = offset + (size_t)n * (KNPTS * 2) * PLANE + pixbase;
    const float* xb   = g_xhwc + (((size_t)n) << 14) * 64;
    const uint32_t sb = smem_u32(smem);

    const int tg = tid >> 4;        // sampling task group 0..15
    const int lh = tid & 15;        // channel quad owner: channels 4lh..4lh+3

    // sampling of one (kn, buf) tile: 128 pixels x 64 ch -> bf16 hi/lo + weights
    auto sample_tile = [&](int kn, int buf) {
        uint32_t* A0 = (uint32_t*)(smem + SM_AH + buf * 16384);
        uint32_t* A1 = (uint32_t*)(smem + SM_AL + buf * 16384);
        uint32_t* B0 = (uint32_t*)(smem + SM_BH + buf * 8192);
        uint32_t* B1 = (uint32_t*)(smem + SM_BL + buf * 8192);
        const float* offy_p = offn + (2 * kn) * PLANE;
        const float* offx_p = offn + (2 * kn + 1) * PLANE;
#pragma unroll
        for (int it = 0; it < 8; it++) {
            const int p = it * 16 + tg;                 // ow == p
            const float iy = (float)ohc + offy_p[p];    // broadcast LDG
            const float ix = (float)p   + offx_p[p];
            const float y0f = floorf(iy), x0f = floorf(ix);
            const float wy1 = iy - y0f,  wx1 = ix - x0f;
            const float wy0 = 1.f - wy1, wx0 = 1.f - wx1;
            const int x0 = (int)x0f, y0 = (int)y0f;
            const int x1 = x0 + 1,  y1 = y0 + 1;
            const float mx0 = ((unsigned)x0 < 128u) ? 1.f : 0.f;
            const float mx1 = ((unsigned)x1 < 128u) ? 1.f : 0.f;
            const float my0 = ((unsigned)y0 < 128u) ? 1.f : 0.f;
            const float my1 = ((unsigned)y1 < 128u) ? 1.f : 0.f;
            const int cx0 = min(max(x0, 0), 127), cx1 = min(max(x1, 0), 127);
            const int cy0 = min(max(y0, 0), 127), cy1 = min(max(y1, 0), 127);
            const float w00 = wx0 * wy0 * mx0 * my0;
            const float w01 = wx1 * wy0 * mx1 * my0;
            const float w10 = wx0 * wy1 * mx0 * my1;
            const float w11 = wx1 * wy1 * mx1 * my1;
            const float4 a = *(const float4*)(xb + (((cy0 << 7) + cx0) << 6) + 4 * lh);
            const float4 b = *(const float4*)(xb + (((cy0 << 7) + cx1) << 6) + 4 * lh);
            const float4 c = *(const float4*)(xb + (((cy1 << 7) + cx0) << 6) + 4 * lh);
            const float4 d = *(const float4*)(xb + (((cy1 << 7) + cx1) << 6) + 4 * lh);
            float v0 = w00 * a.x + w01 * b.x + w10 * c.x + w11 * d.x;
            float v1 = w00 * a.y + w01 * b.y + w10 * c.y + w11 * d.y;
            float v2 = w00 * a.z + w01 * b.z + w10 * c.z + w11 * d.z;
            float v3 = w00 * a.w + w01 * b.w + w10 * c.w + w11 * d.w;
            uint2 hi, lo;
            hi.x = pack_bf16x2(v0, v1);
            hi.y = pack_bf16x2(v2, v3);
            lo.x = pack_bf16x2(v0 - unpack_lo(hi.x), v1 - unpack_hi(hi.x));
            lo.y = pack_bf16x2(v2 - unpack_lo(hi.y), v3 - unpack_hi(hi.y));
            const int wix = AIDX(p, 2 * lh);
            *(uint2*)&A0[wix] = hi;
            *(uint2*)&A1[wix] = lo;
        }
        // stage weight chunk (packed bf16 pairs)
#pragma unroll
        for (int k = 0; k < 4; k++) {
            const int i = tid + k * 256;
            const int oc = i >> 4, q = i & 15;
            const int wix = BIDX(oc, 2 * q);
            const int gi  = (kn << 11) + (oc << 5) + 2 * q;
            *(uint2*)&B0[wix] = *(const uint2*)&g_w0[gi];
            *(uint2*)&B1[wix] = *(const uint2*)&g_w1[gi];
        }
    };

    // GEMM lane constants
    const int m0 = (wid & 3) * 32;
    const int n0 = (wid >> 2) * 32;
    const int r  = lane >> 2;
    const int u  = lane & 3;
    const int l7   = lane & 7;
    const int swz  = l7 << 2;
    const int arow0 = m0 + l7 + (((lane >> 3) & 1) << 3);
    const int kbA   = ((lane >> 4) & 1) << 2;
    const int browl = n0 + l7;
    const int kbB   = ((lane >> 3) & 1) << 2;

    float acc[2][4][4];
#pragma unroll
    for (int mt = 0; mt < 2; mt++)
#pragma unroll
        for (int nt = 0; nt < 4; nt++)
#pragma unroll
            for (int q = 0; q < 4; q++) acc[mt][nt][q] = 0.f;

    // prologue: fill buffer 0 with kn=0
    sample_tile(0, 0);
    __syncthreads();

    for (int kn = 0; kn < KNPTS; kn++) {
        const int buf = kn & 1;
        const uint32_t a0b = sb + SM_AH + buf * 16384;
        const uint32_t a1b = sb + SM_AL + buf * 16384;
        const uint32_t b0b = sb + SM_BH + buf * 8192;
        const uint32_t b1b = sb + SM_BL + buf * 8192;

        // ---- GEMM(kn) from buf ----
#pragma unroll
        for (int ks = 0; ks < 4; ks++) {
            uint32_t a0[2][4], a1[2][4];
#pragma unroll
            for (int mt = 0; mt < 2; mt++) {
                const int row = arow0 + mt * 16;
                const uint32_t off =
                    (uint32_t)(((row << 5) + ((ks * 8 + kbA) ^ swz)) << 2);
                ldm4(a0[mt], a0b + off);
                ldm4(a1[mt], a1b + off);
            }
            uint32_t b0[4][2], b1[4][2];
#pragma unroll
            for (int nt = 0; nt < 4; nt++) {
                const int row = browl + nt * 8;
                const uint32_t off =
                    (uint32_t)(((row << 5) + ((ks * 8 + kbB) ^ swz)) << 2);
                ldm2(b0[nt], b0b + off);
                ldm2(b1[nt], b1b + off);
            }
#pragma unroll
            for (int mt = 0; mt < 2; mt++)
#pragma unroll
                for (int nt = 0; nt < 4; nt++) {
                    MMA(acc[mt][nt], a1[mt], b0[nt]);   // lo-x * hi-w
                    MMA(acc[mt][nt], a0[mt], b1[nt]);   // hi-x * lo-w
                    MMA(acc[mt][nt], a0[mt], b0[nt]);   // hi-x * hi-w
                }
        }

        // ---- sample(kn+1) into the other buffer (overlaps MMA tail) ----
        if (kn + 1 < KNPTS) sample_tile(kn + 1, buf ^ 1);
        __syncthreads();
    }

    // ---- epilogue: stage C in smem (oc-major), then coalesced STG.128 ----
    float* Cs = (float*)smem;   // tiles dead after final sync
#pragma unroll
    for (int mt = 0; mt < 2; mt++)
#pragma unroll
        for (int nt = 0; nt < 4; nt++) {
            const int p  = m0 + mt * 16 + r;
            const int oc = n0 + nt * 8 + 2 * u;
            Cs[oc * CS_STRIDE + p]           = acc[mt][nt][0];
            Cs[(oc + 1) * CS_STRIDE + p]     = acc[mt][nt][1];
            Cs[oc * CS_STRIDE + p + 8]       = acc[mt][nt][2];
            Cs[(oc + 1) * CS_STRIDE + p + 8] = acc[mt][nt][3];
        }
    __syncthreads();
    float* ob = out + (((size_t)n * OC) << 14) + pixbase;
#pragma unroll
    for (int k = 0; k < 8; k++) {
        const int idx = tid + k * 256;
        const int oc = idx >> 5, fq = idx & 31;
        const float4 v = *(const float4*)(Cs + oc * CS_STRIDE + fq * 4);
        *(float4*)(ob + ((size_t)oc << 14) + fq * 4) = v;
    }
}

extern "C" void kernel_launch(void* const* d_in, const int* in_sizes, int n_in,
                              void* d_out, int out_size)
{
    const float* x      = (const float*)d_in[0];   // (4, 64, 128, 128)
    const float* offset = (const float*)d_in[1];   // (4, 18, 128, 128)
    const float* weight = (const float*)d_in[2];   // (64, 64, 9)
    float* out = (float*)d_out;                    // (4, 64, 128, 128)
    (void)in_sizes; (void)n_in; (void)out_size;

    static int smem_set = 0;
    if (!smem_set) {
        cudaFuncSetAttribute(dcn_mma_kernel,
                             cudaFuncAttributeMaxDynamicSharedMemorySize, SM_TOTAL);
        smem_set = 1;
    }
    nchw_to_nhwc_kernel<<<4 * 256, 256>>>(x);
    wsplit_kernel<<<(KNPTS * OC * 32 + 255) / 256, 256>>>(weight);
    dcn_mma_kernel<<<NBLK, THREADS, SM_TOTAL>>>(offset, out);
}